// round 4
// baseline (speedup 1.0000x reference)
#include <cuda_runtime.h>
#include <cstdint>
#include <cstddef>

#define TOKENS 8192
#define DIN    4096
#define DOUT   16384

// ---------------- device scratch (static: no runtime allocation) ----------------
static __device__ int8_t g_A1[(size_t)TOKENS * DIN];   // 32 MB  digit-1 of x
static __device__ int8_t g_A2[(size_t)TOKENS * DIN];   // 32 MB  digit-2 (residual) of x
static __device__ int8_t g_W8[(size_t)DOUT   * DIN];   // 64 MB  int8 weights (exact)
static __device__ float  g_s1[TOKENS];                 // per-token scale

// ---------------- helpers ----------------
__device__ __forceinline__ uint32_t smem_u32(const void* p) {
    uint32_t a;
    asm("{ .reg .u64 t; cvta.to.shared.u64 t, %1; cvt.u32.u64 %0, t; }" : "=r"(a) : "l"(p));
    return a;
}
__device__ __forceinline__ void bulk64(uint32_t dst, const void* src, uint32_t mbar) {
    asm volatile(
        "cp.async.bulk.shared::cluster.global.mbarrier::complete_tx::bytes [%0], [%1], 64, [%2];"
        :: "r"(dst), "l"(src), "r"(mbar) : "memory");
}
__device__ __forceinline__ void expect_tx(uint32_t mbar, uint32_t bytes) {
    asm volatile("mbarrier.arrive.expect_tx.shared.b64 _, [%0], %1;"
                 :: "r"(mbar), "r"(bytes) : "memory");
}
__device__ __forceinline__ void mbar_init(uint32_t addr, uint32_t cnt) {
    asm volatile("mbarrier.init.shared.b64 [%0], %1;" :: "r"(addr), "r"(cnt) : "memory");
}
__device__ __forceinline__ void mbar_wait(uint32_t addr, uint32_t parity) {
    asm volatile(
        "{\n\t.reg .pred P;\n\t"
        "LAB_WAIT_%=:\n\t"
        "mbarrier.try_wait.parity.acquire.cta.shared::cta.b64 P, [%0], %1, 0x989680;\n\t"
        "@P bra.uni LAB_DONE_%=;\n\t"
        "bra.uni LAB_WAIT_%=;\n\t"
        "LAB_DONE_%=:\n\t}"
        :: "r"(addr), "r"(parity) : "memory");
}
__device__ __forceinline__ void ldsm4(uint32_t& r0, uint32_t& r1, uint32_t& r2, uint32_t& r3,
                                      uint32_t addr) {
    asm volatile("ldmatrix.sync.aligned.m8n8.x4.shared.b16 {%0,%1,%2,%3}, [%4];"
                 : "=r"(r0), "=r"(r1), "=r"(r2), "=r"(r3) : "r"(addr));
}
__device__ __forceinline__ void imma16832(int* d, const uint32_t* a, const uint32_t* b) {
    asm volatile(
        "mma.sync.aligned.m16n8k32.row.col.s32.s8.s8.s32 "
        "{%0,%1,%2,%3}, {%4,%5,%6,%7}, {%8,%9}, {%0,%1,%2,%3};"
        : "+r"(d[0]), "+r"(d[1]), "+r"(d[2]), "+r"(d[3])
        : "r"(a[0]), "r"(a[1]), "r"(a[2]), "r"(a[3]), "r"(b[0]), "r"(b[1]));
}

// ---------------- convert kernels ----------------
__global__ void __launch_bounds__(256) convert_w_kernel(const int* __restrict__ q) {
    size_t i = (size_t)blockIdx.x * 256 + threadIdx.x;   // one int4 -> char4
    int4 v = ((const int4*)q)[i];
    char4 o;
    o.x = (char)v.x; o.y = (char)v.y; o.z = (char)v.z; o.w = (char)v.w;
    ((char4*)g_W8)[i] = o;
}

__global__ void __launch_bounds__(256) quant_x_kernel(const float* __restrict__ x) {
    const int t = blockIdx.x;                            // one token per CTA
    const float4* row = (const float4*)(x + (size_t)t * DIN);
    float4 v[4];
    float m = 0.f;
#pragma unroll
    for (int j = 0; j < 4; ++j) {
        v[j] = row[threadIdx.x + j * 256];
        m = fmaxf(m, fmaxf(fmaxf(fabsf(v[j].x), fabsf(v[j].y)),
                           fmaxf(fabsf(v[j].z), fabsf(v[j].w))));
    }
#pragma unroll
    for (int o = 16; o > 0; o >>= 1) m = fmaxf(m, __shfl_xor_sync(0xFFFFFFFFu, m, o));
    __shared__ float wmax[8];
    if ((threadIdx.x & 31) == 0) wmax[threadIdx.x >> 5] = m;
    __syncthreads();
    float amax = wmax[0];
#pragma unroll
    for (int w = 1; w < 8; ++w) amax = fmaxf(amax, wmax[w]);
    amax = fmaxf(amax, 1e-30f);

    const float s1   = amax * (1.f / 127.f);
    const float inv1 = 127.f / amax;
    const float inv2 = 254.f / s1;
    if (threadIdx.x == 0) g_s1[t] = s1;

    char4* o1 = (char4*)(g_A1 + (size_t)t * DIN);
    char4* o2 = (char4*)(g_A2 + (size_t)t * DIN);
#pragma unroll
    for (int j = 0; j < 4; ++j) {
        float f[4] = {v[j].x, v[j].y, v[j].z, v[j].w};
        char  c1[4], c2[4];
#pragma unroll
        for (int e = 0; e < 4; ++e) {
            float q1 = rintf(f[e] * inv1);
            float r  = fmaf(-q1, s1, f[e]);
            float q2 = rintf(r * inv2);
            q2 = fminf(fmaxf(q2, -127.f), 127.f);
            c1[e] = (char)(int)q1;
            c2[e] = (char)(int)q2;
        }
        o1[threadIdx.x + j * 256] = make_char4(c1[0], c1[1], c1[2], c1[3]);
        o2[threadIdx.x + j * 256] = make_char4(c2[0], c2[1], c2[2], c2[3]);
    }
}

// ---------------- GEMM ----------------
// CTA tile 256(M: 128 tokens x 2 digits) x 128(N), K-tile 64.
// 256 threads = 8 warps (4 row-bands x 2 col-bands), warp tile 64x64.
// 128 acc regs/thread + frags -> ~190 regs, NO spills (512-thread version spilled).
// Loads: cp.async.bulk 64B rows + mbarrier 5-stage pipeline; reads: ldmatrix.x4.
static constexpr int PITCH       = 80;
static constexpr int A_ROWS      = 256;
static constexpr int B_ROWS      = 128;
static constexpr int A_BYTES     = A_ROWS * PITCH;        // 20480
static constexpr int STAGE_BYTES = (A_ROWS + B_ROWS) * PITCH;  // 30720
static constexpr int STAGES      = 5;
static constexpr int MBAR_OFF    = STAGES * STAGE_BYTES;  // 153600
static constexpr int S1_OFF      = MBAR_OFF + 64;
static constexpr int SMEM_BYTES  = S1_OFF + 512;          // 154176
static constexpr int EPI_PITCH   = 132;                   // floats
static constexpr int KTILES      = DIN / 64;              // 64

__global__ void __launch_bounds__(256, 1)
qlinear_gemm(const int* __restrict__ q_bias, const float* __restrict__ scale,
             const float* __restrict__ bias_scale, float* __restrict__ out)
{
    extern __shared__ char smem[];
    const uint32_t sb = smem_u32(smem);
    const int tid  = threadIdx.x;
    const int wid  = tid >> 5;
    const int lane = tid & 31;
    const int wrow = wid >> 1;            // 0..3 : rows 64*wrow..+63
    const int wcol = wid & 1;             // 0..1 : cols 64*wcol..+63

    // grouped rasterization: 8 M-tiles per group so A + W slices stay in L2
    const int bid   = blockIdx.x;
    const int group = bid >> 10;          // 8 m-tiles * 128 n-tiles
    const int m0    = ((group << 3) + (bid & 7)) * 128;     // token base
    const int n0    = ((bid >> 3) & 127) * 128;

    if (tid == 0) {
#pragma unroll
        for (int s = 0; s < STAGES; ++s) mbar_init(sb + MBAR_OFF + s * 8, 8);
    }
    float* s1_sm = (float*)(smem + S1_OFF);
    if (tid < 128) s1_sm[tid] = g_s1[m0 + tid];
    __syncthreads();

    // producer setup: each warp owns 48 rows; lane r0 always, r1 only if lane<16
    const int row0 = wid * 48 + lane;
    const int row1 = row0 + 32;
    const int8_t* src0;
    const int8_t* src1 = nullptr;
    uint32_t dst0, dst1 = 0;
    {
        src0 = (row0 < 128) ? g_A1 + (size_t)(m0 + row0) * DIN
             : (row0 < 256) ? g_A2 + (size_t)(m0 + row0 - 128) * DIN
                            : g_W8 + (size_t)(n0 + row0 - 256) * DIN;
        dst0 = (row0 < 256) ? (uint32_t)row0 * PITCH
                            : A_BYTES + (uint32_t)(row0 - 256) * PITCH;
        if (lane < 16) {
            src1 = (row1 < 128) ? g_A1 + (size_t)(m0 + row1) * DIN
                 : (row1 < 256) ? g_A2 + (size_t)(m0 + row1 - 128) * DIN
                                : g_W8 + (size_t)(n0 + row1 - 256) * DIN;
            dst1 = (row1 < 256) ? (uint32_t)row1 * PITCH
                                : A_BYTES + (uint32_t)(row1 - 256) * PITCH;
        }
    }

    // prologue: fill stages 0..3 (k-tiles 0..3)
#pragma unroll
    for (int s = 0; s < 4; ++s) {
        const uint32_t mb = sb + MBAR_OFF + s * 8;
        if (lane == 0) expect_tx(mb, 48 * 64);
        __syncwarp();
        bulk64(sb + s * STAGE_BYTES + dst0, src0 + s * 64, mb);
        if (lane < 16) bulk64(sb + s * STAGE_BYTES + dst1, src1 + s * 64, mb);
    }

    // ldmatrix per-lane offsets
    const uint32_t aoff = (uint32_t)((lane & 15) * PITCH + (lane >> 4) * 16
                                     + wrow * 64 * PITCH);
    const uint32_t boff = (uint32_t)((wcol * 64 + (lane >> 4) * 8 + (lane & 7)) * PITCH
                                     + ((lane >> 3) & 1) * 16);

    int acc[4][8][4] = {};
    int cbuf = 0, cph = 0, pbuf = 4;

#pragma unroll 1
    for (int i = 0; i < KTILES; ++i) {
        __syncthreads();                          // buffer (i+4)%5 free for refill
        const int nxt = i + 4;
        if (nxt < KTILES) {
            const uint32_t mb = sb + MBAR_OFF + pbuf * 8;
            if (lane == 0) expect_tx(mb, 48 * 64);
            __syncwarp();
            bulk64(sb + pbuf * STAGE_BYTES + dst0, src0 + nxt * 64, mb);
            if (lane < 16) bulk64(sb + pbuf * STAGE_BYTES + dst1, src1 + nxt * 64, mb);
            pbuf = (pbuf + 1 == STAGES) ? 0 : pbuf + 1;
        }
        mbar_wait(sb + MBAR_OFF + cbuf * 8, cph);

        const uint32_t sA = sb + cbuf * STAGE_BYTES;
        const uint32_t sB = sA + A_BYTES;
#pragma unroll
        for (int ks = 0; ks < 2; ++ks) {
            uint32_t b[8][2];
#pragma unroll
            for (int p = 0; p < 4; ++p)
                ldsm4(b[2*p][0], b[2*p][1], b[2*p+1][0], b[2*p+1][1],
                      sB + boff + ks * 32 + p * 16 * PITCH);
#pragma unroll
            for (int mt = 0; mt < 4; ++mt) {
                uint32_t a[4];
                ldsm4(a[0], a[1], a[2], a[3], sA + aoff + ks * 32 + mt * 16 * PITCH);
#pragma unroll
                for (int nt = 0; nt < 8; ++nt)
                    imma16832(acc[mt][nt], a, b[nt]);
            }
        }
        if (++cbuf == STAGES) { cbuf = 0; cph ^= 1; }
    }
    __syncthreads();

    // ---------------- epilogue ----------------
    const float sc  = scale[0];
    const float bsc = bias_scale[0];
    const int r  = lane >> 2;             // 0..7
    const int kg = lane & 3;              // 0..3
    float* stage = (float*)smem;          // 128 x 132 floats (reuses pipeline smem)

    if (wrow >= 2) {                      // digit-2: write s2*acc to SMEM
#pragma unroll
        for (int mt = 0; mt < 4; ++mt) {
            const int t0 = (wrow - 2) * 64 + mt * 16 + r;
            const float s2a = s1_sm[t0]     * (1.f / 254.f);
            const float s2b = s1_sm[t0 + 8] * (1.f / 254.f);
#pragma unroll
            for (int nt = 0; nt < 8; ++nt) {
                const int col = wcol * 64 + nt * 8 + kg * 2;
                float2 p0 = make_float2(acc[mt][nt][0] * s2a, acc[mt][nt][1] * s2a);
                float2 p1 = make_float2(acc[mt][nt][2] * s2b, acc[mt][nt][3] * s2b);
                *(float2*)(stage + (size_t)t0 * EPI_PITCH + col)       = p0;
                *(float2*)(stage + (size_t)(t0 + 8) * EPI_PITCH + col) = p1;
            }
        }
    }
    __syncthreads();

    if (wrow < 2) {                       // digit-1: combine + bias + store
#pragma unroll
        for (int nt = 0; nt < 8; ++nt) {
            const int col = wcol * 64 + nt * 8 + kg * 2;
            const int2 qb = *(const int2*)(q_bias + n0 + col);
            const float b0 = qb.x * bsc, b1 = qb.y * bsc;
#pragma unroll
            for (int mt = 0; mt < 4; ++mt) {
                const int t0 = wrow * 64 + mt * 16 + r;
                const float s1a = s1_sm[t0], s1b = s1_sm[t0 + 8];
                const float* st0 = stage + (size_t)t0 * EPI_PITCH + col;
                const float* st1 = stage + (size_t)(t0 + 8) * EPI_PITCH + col;
                float2 r0, r1;
                r0.x = sc * fmaf(acc[mt][nt][0], s1a, st0[0]) + b0;
                r0.y = sc * fmaf(acc[mt][nt][1], s1a, st0[1]) + b1;
                r1.x = sc * fmaf(acc[mt][nt][2], s1b, st1[0]) + b0;
                r1.y = sc * fmaf(acc[mt][nt][3], s1b, st1[1]) + b1;
                *(float2*)(out + (size_t)(m0 + t0) * DOUT + n0 + col)     = r0;
                *(float2*)(out + (size_t)(m0 + t0 + 8) * DOUT + n0 + col) = r1;
            }
        }
    }
}

// ---------------- launch ----------------
extern "C" void kernel_launch(void* const* d_in, const int* in_sizes, int n_in,
                              void* d_out, int out_size) {
    const float* x   = (const float*)d_in[0];
    const int*   qw  = (const int*)d_in[1];
    const int*   qb  = (const int*)d_in[2];
    const float* sc  = (const float*)d_in[3];
    const float* bsc = (const float*)d_in[4];
    float* out = (float*)d_out;

    cudaFuncSetAttribute(qlinear_gemm, cudaFuncAttributeMaxDynamicSharedMemorySize, SMEM_BYTES);

    convert_w_kernel<<<(DOUT * (size_t)DIN) / 4 / 256, 256>>>(qw);   // 65536 blocks
    quant_x_kernel<<<TOKENS, 256>>>(x);                              // 8192 blocks
    qlinear_gemm<<<(TOKENS / 128) * (DOUT / 128), 256, SMEM_BYTES>>>(qb, sc, bsc, out);
}

// round 7
// speedup vs baseline: 1.2563x; 1.2563x over previous
#include <cuda_runtime.h>
#include <cstdint>
#include <cstddef>

#define TOKENS 8192
#define DIN    4096
#define DOUT   16384

// ---------------- device scratch (static: no runtime allocation) ----------------
// Packed layouts: 128x128 int8 blocks (16 KB), SW128-swizzled inside each block.
// g_A1p/g_A2p: block(mt, kt) at ((mt*32 + kt) * 16384)   [mt: 64, kt: 32]
// g_W8p:       block(nt, kt) at ((nt*32 + kt) * 16384)   [nt: 128, kt: 32]
static __device__ int8_t g_A1p[(size_t)TOKENS * DIN];   // 32 MB
static __device__ int8_t g_A2p[(size_t)TOKENS * DIN];   // 32 MB
static __device__ int8_t g_W8p[(size_t)DOUT   * DIN];   // 64 MB
static __device__ float  g_s1[TOKENS];

// ---------------- PTX helpers ----------------
__device__ __forceinline__ uint32_t smem_u32(const void* p) {
    uint32_t a;
    asm("{ .reg .u64 t; cvta.to.shared.u64 t, %1; cvt.u32.u64 %0, t; }" : "=r"(a) : "l"(p));
    return a;
}
__device__ __forceinline__ void bulk_cp(uint32_t dst, const void* src, uint32_t bytes,
                                        uint32_t mbar) {
    asm volatile(
        "cp.async.bulk.shared::cluster.global.mbarrier::complete_tx::bytes [%0], [%1], %2, [%3];"
        :: "r"(dst), "l"(src), "r"(bytes), "r"(mbar) : "memory");
}
__device__ __forceinline__ void expect_tx(uint32_t mbar, uint32_t bytes) {
    asm volatile("mbarrier.arrive.expect_tx.shared.b64 _, [%0], %1;"
                 :: "r"(mbar), "r"(bytes) : "memory");
}
__device__ __forceinline__ void mbar_init(uint32_t addr, uint32_t cnt) {
    asm volatile("mbarrier.init.shared.b64 [%0], %1;" :: "r"(addr), "r"(cnt) : "memory");
}
__device__ __forceinline__ void mbar_wait(uint32_t addr, uint32_t parity) {
    asm volatile(
        "{\n\t.reg .pred P;\n\t"
        "LAB_WAIT_%=:\n\t"
        "mbarrier.try_wait.parity.acquire.cta.shared::cta.b64 P, [%0], %1, 0x989680;\n\t"
        "@P bra.uni LAB_DONE_%=;\n\t"
        "bra.uni LAB_WAIT_%=;\n\t"
        "LAB_DONE_%=:\n\t}"
        :: "r"(addr), "r"(parity) : "memory");
}
__device__ __forceinline__ void ldsm4(uint32_t& r0, uint32_t& r1, uint32_t& r2, uint32_t& r3,
                                      uint32_t addr) {
    asm volatile("ldmatrix.sync.aligned.m8n8.x4.shared.b16 {%0,%1,%2,%3}, [%4];"
                 : "=r"(r0), "=r"(r1), "=r"(r2), "=r"(r3) : "r"(addr));
}
__device__ __forceinline__ void imma16832(int* d, const uint32_t* a, const uint32_t* b) {
    asm volatile(
        "mma.sync.aligned.m16n8k32.row.col.s32.s8.s8.s32 "
        "{%0,%1,%2,%3}, {%4,%5,%6,%7}, {%8,%9}, {%0,%1,%2,%3};"
        : "+r"(d[0]), "+r"(d[1]), "+r"(d[2]), "+r"(d[3])
        : "r"(a[0]), "r"(a[1]), "r"(a[2]), "r"(a[3]), "r"(b[0]), "r"(b[1]));
}

// ---------------- convert kernels (write packed + swizzled) ----------------
__global__ void __launch_bounds__(256) convert_w_kernel(const int* __restrict__ q) {
    size_t i = (size_t)blockIdx.x * 256 + threadIdx.x;   // char4 index
    int4 v = ((const int4*)q)[i];
    char4 o;
    o.x = (char)v.x; o.y = (char)v.y; o.z = (char)v.z; o.w = (char)v.w;
    const int n  = (int)(i >> 10);            // row in W (DIN/4 = 1024 char4 per row)
    const int k  = ((int)i & 1023) * 4;
    const int nt = n >> 7, r = n & 127, kt = k >> 7, kl = k & 127;
    const size_t blk = ((size_t)nt * 32 + kt) * 16384;
    const uint32_t off = (uint32_t)(r * 128 + (kl ^ ((r & 7) << 4)));
    *(char4*)(g_W8p + blk + off) = o;
}

__global__ void __launch_bounds__(256) quant_x_kernel(const float* __restrict__ x) {
    const int t = blockIdx.x;                            // one token per CTA
    const float4* row = (const float4*)(x + (size_t)t * DIN);
    float4 v[4];
    float m = 0.f;
#pragma unroll
    for (int j = 0; j < 4; ++j) {
        v[j] = row[threadIdx.x + j * 256];
        m = fmaxf(m, fmaxf(fmaxf(fabsf(v[j].x), fabsf(v[j].y)),
                           fmaxf(fabsf(v[j].z), fabsf(v[j].w))));
    }
#pragma unroll
    for (int o = 16; o > 0; o >>= 1) m = fmaxf(m, __shfl_xor_sync(0xFFFFFFFFu, m, o));
    __shared__ float wmax[8];
    if ((threadIdx.x & 31) == 0) wmax[threadIdx.x >> 5] = m;
    __syncthreads();
    float amax = wmax[0];
#pragma unroll
    for (int w = 1; w < 8; ++w) amax = fmaxf(amax, wmax[w]);
    amax = fmaxf(amax, 1e-30f);

    const float s1   = amax * (1.f / 127.f);
    const float inv1 = 127.f / amax;
    const float inv2 = 254.f / s1;
    if (threadIdx.x == 0) g_s1[t] = s1;

    const int mt = t >> 7, r = t & 127;
    const size_t rowoff = (size_t)(mt * 32) * 16384 + (uint32_t)(r * 128);
    const uint32_t rx = (uint32_t)((r & 7) << 4);
#pragma unroll
    for (int j = 0; j < 4; ++j) {
        float f[4] = {v[j].x, v[j].y, v[j].z, v[j].w};
        char  c1[4], c2[4];
#pragma unroll
        for (int e = 0; e < 4; ++e) {
            float q1 = rintf(f[e] * inv1);
            float rr = fmaf(-q1, s1, f[e]);
            float q2 = rintf(rr * inv2);
            q2 = fminf(fmaxf(q2, -127.f), 127.f);
            c1[e] = (char)(int)q1;
            c2[e] = (char)(int)q2;
        }
        const int k  = (threadIdx.x + j * 256) * 4;
        const int kt = k >> 7, kl = k & 127;
        const size_t off = rowoff + (size_t)kt * 16384 + (kl ^ rx);
        *(char4*)(g_A1p + off) = make_char4(c1[0], c1[1], c1[2], c1[3]);
        *(char4*)(g_A2p + off) = make_char4(c2[0], c2[1], c2[2], c2[3]);
    }
}

// ---------------- GEMM ----------------
// CTA tile 256(M: 128 tokens x 2 digits) x 128(N), K-tile 128, 32 iters.
// 512 threads = 16 warps (4 row-bands x 4 col-bands), warp tile 64x32.
// Stage = A1(16K) + A2(16K) + B(16K) = 48K filled by THREE 16KB bulk copies.
static constexpr int STAGE_BYTES = 49152;
static constexpr int STAGES      = 4;
static constexpr int MBAR_OFF    = STAGES * STAGE_BYTES;       // 196608
static constexpr int S1_OFF      = MBAR_OFF + 64;
static constexpr int SMEM_BYTES  = S1_OFF + 512;               // 197184
static constexpr int EPI_PITCH   = 132;                        // floats
static constexpr int KTILES      = DIN / 128;                  // 32

__global__ void __launch_bounds__(512, 1)
qlinear_gemm(const int* __restrict__ q_bias, const float* __restrict__ scale,
             const float* __restrict__ bias_scale, float* __restrict__ out,
             int m_base)
{
    extern __shared__ char smem[];
    const uint32_t sb = smem_u32(smem);
    const int tid  = threadIdx.x;
    const int wid  = tid >> 5;
    const int lane = tid & 31;
    const int wrow = wid >> 2;            // 0..3 : rows 64*wrow..+63 (of 256)
    const int wcol = wid & 3;             // 0..3 : cols 32*wcol..+31

    // rasterization: 8 m-tiles per group (within this launch's 16 m-tiles)
    const int bid    = blockIdx.x;
    const int group  = bid >> 10;
    const int m_tile = (group << 3) + (bid & 7);
    const int n_tile = (bid >> 3) & 127;
    const int m0     = m_base + m_tile * 128;
    const int n0     = n_tile * 128;

    if (tid == 0) {
#pragma unroll
        for (int s = 0; s < STAGES; ++s) mbar_init(sb + MBAR_OFF + s * 8, 1);
    }
    float* s1_sm = (float*)(smem + S1_OFF);
    if (tid < 128) s1_sm[tid] = g_s1[m0 + tid];
    __syncthreads();

    // block sources (contiguous in kt)
    const int8_t* a1src = g_A1p + ((size_t)(m0 >> 7) * 32) * 16384;
    const int8_t* a2src = g_A2p + ((size_t)(m0 >> 7) * 32) * 16384;
    const int8_t* wsrc  = g_W8p + ((size_t)n_tile * 32) * 16384;

    // prologue: fill stages 0..2
    if (tid == 0) {
#pragma unroll
        for (int s = 0; s < 3; ++s) {
            const uint32_t mb  = sb + MBAR_OFF + s * 8;
            const uint32_t dst = sb + s * STAGE_BYTES;
            expect_tx(mb, STAGE_BYTES);
            bulk_cp(dst,         a1src + (size_t)s * 16384, 16384, mb);
            bulk_cp(dst + 16384, a2src + (size_t)s * 16384, 16384, mb);
            bulk_cp(dst + 32768, wsrc  + (size_t)s * 16384, 16384, mb);
        }
    }

    // per-lane operand addressing (swizzle folded into kl-XOR, constant per lane)
    const int ar = wrow * 64 + (lane & 15);          // 0..255
    const uint32_t aRowBase = (uint32_t)((ar >> 7) * 16384 + (ar & 127) * 128);
    const uint32_t axor = (uint32_t)((ar & 7) << 4);
    const uint32_t aklb = (uint32_t)((lane >> 4) * 16);
    const int br = wcol * 32 + ((lane >> 4) << 3) + (lane & 7);   // 0..127
    const uint32_t bRowBase = (uint32_t)(32768 + br * 128);
    const uint32_t bxor = (uint32_t)((br & 7) << 4);
    const uint32_t bklb = (uint32_t)(((lane >> 3) & 1) * 16);
    uint32_t akl[4], bkl[4];
#pragma unroll
    for (int ks = 0; ks < 4; ++ks) {
        akl[ks] = (aklb + ks * 32) ^ axor;
        bkl[ks] = (bklb + ks * 32) ^ bxor;
    }

    int acc[4][4][4] = {};
    int cph = 0;

#pragma unroll 1
    for (int i = 0; i < KTILES; ++i) {
        const int cbuf = i & 3;
        __syncthreads();                              // buf (i+3)&3 fully consumed
        const int nxt = i + 3;
        if (nxt < KTILES && tid == 0) {
            const int pb = nxt & 3;
            const uint32_t mb  = sb + MBAR_OFF + pb * 8;
            const uint32_t dst = sb + pb * STAGE_BYTES;
            expect_tx(mb, STAGE_BYTES);
            bulk_cp(dst,         a1src + (size_t)nxt * 16384, 16384, mb);
            bulk_cp(dst + 16384, a2src + (size_t)nxt * 16384, 16384, mb);
            bulk_cp(dst + 32768, wsrc  + (size_t)nxt * 16384, 16384, mb);
        }
        mbar_wait(sb + MBAR_OFF + cbuf * 8, cph);
        if (cbuf == 3) cph ^= 1;

        const uint32_t stg = sb + (uint32_t)cbuf * STAGE_BYTES;
#pragma unroll
        for (int ks = 0; ks < 4; ++ks) {
            uint32_t b[4][2];
            // Sequential pairing (matches passing R4 layout): first ldsm covers
            // band rows 0-15 -> b[0] (rows 0-7), b[1] (rows 8-15); second covers
            // rows 16-31 -> b[2], b[3].  (R5 had b[0],b[2]/b[1],b[3]: half the
            // columns swapped -> rel_err 1.0.)
            ldsm4(b[0][0], b[0][1], b[1][0], b[1][1], stg + bRowBase + bkl[ks]);
            ldsm4(b[2][0], b[2][1], b[3][0], b[3][1], stg + bRowBase + 2048 + bkl[ks]);
#pragma unroll
            for (int mt = 0; mt < 4; ++mt) {
                uint32_t a[4];
                ldsm4(a[0], a[1], a[2], a[3], stg + aRowBase + mt * 2048 + akl[ks]);
                imma16832(acc[mt][0], a, b[0]);
                imma16832(acc[mt][1], a, b[1]);
                imma16832(acc[mt][2], a, b[2]);
                imma16832(acc[mt][3], a, b[3]);
            }
        }
    }
    __syncthreads();

    // ---------------- epilogue ----------------
    const float sc  = scale[0];
    const float bsc = bias_scale[0];
    const int r  = lane >> 2;             // 0..7
    const int kg = lane & 3;              // 0..3
    float* stage = (float*)smem;          // 128 x 132 floats (reuses pipeline smem)

    if (wrow >= 2) {                      // digit-2: write s2*acc to SMEM
#pragma unroll
        for (int mt = 0; mt < 4; ++mt) {
            const int t0 = (wrow - 2) * 64 + mt * 16 + r;
            const float s2a = s1_sm[t0]     * (1.f / 254.f);
            const float s2b = s1_sm[t0 + 8] * (1.f / 254.f);
#pragma unroll
            for (int nt = 0; nt < 4; ++nt) {
                const int col = wcol * 32 + nt * 8 + kg * 2;
                float2 p0 = make_float2(acc[mt][nt][0] * s2a, acc[mt][nt][1] * s2a);
                float2 p1 = make_float2(acc[mt][nt][2] * s2b, acc[mt][nt][3] * s2b);
                *(float2*)(stage + (size_t)t0 * EPI_PITCH + col)       = p0;
                *(float2*)(stage + (size_t)(t0 + 8) * EPI_PITCH + col) = p1;
            }
        }
    }
    __syncthreads();

    if (wrow < 2) {                       // digit-1: combine + bias + store
#pragma unroll
        for (int nt = 0; nt < 4; ++nt) {
            const int col = wcol * 32 + nt * 8 + kg * 2;
            const int2 qb = *(const int2*)(q_bias + n0 + col);
            const float b0 = qb.x * bsc, b1 = qb.y * bsc;
#pragma unroll
            for (int mt = 0; mt < 4; ++mt) {
                const int t0 = wrow * 64 + mt * 16 + r;
                const float s1a = s1_sm[t0], s1b = s1_sm[t0 + 8];
                const float* st0 = stage + (size_t)t0 * EPI_PITCH + col;
                const float* st1 = stage + (size_t)(t0 + 8) * EPI_PITCH + col;
                float2 r0, r1;
                r0.x = sc * fmaf(acc[mt][nt][0], s1a, st0[0]) + b0;
                r0.y = sc * fmaf(acc[mt][nt][1], s1a, st0[1]) + b1;
                r1.x = sc * fmaf(acc[mt][nt][2], s1b, st1[0]) + b0;
                r1.y = sc * fmaf(acc[mt][nt][3], s1b, st1[1]) + b1;
                *(float2*)(out + (size_t)(m0 + t0) * DOUT + n0 + col)     = r0;
                *(float2*)(out + (size_t)(m0 + t0 + 8) * DOUT + n0 + col) = r1;
            }
        }
    }
}

// ---------------- launch ----------------
extern "C" void kernel_launch(void* const* d_in, const int* in_sizes, int n_in,
                              void* d_out, int out_size) {
    const float* x   = (const float*)d_in[0];
    const int*   qw  = (const int*)d_in[1];
    const int*   qb  = (const int*)d_in[2];
    const float* sc  = (const float*)d_in[3];
    const float* bsc = (const float*)d_in[4];
    float* out = (float*)d_out;

    cudaFuncSetAttribute(qlinear_gemm, cudaFuncAttributeMaxDynamicSharedMemorySize, SMEM_BYTES);

    convert_w_kernel<<<(DOUT * (size_t)DIN) / 4 / 256, 256>>>(qw);   // 65536 blocks
    quant_x_kernel<<<TOKENS, 256>>>(x);                              // 8192 blocks
    // GEMM split into 4 M-chunks (2048 tokens each) so ncu (-s 5 -c 1) lands on it.
    for (int c = 0; c < 4; ++c)
        qlinear_gemm<<<16 * 128, 512, SMEM_BYTES>>>(qb, sc, bsc, out, c * 2048);
}

// round 8
// speedup vs baseline: 6.6882x; 5.3237x over previous
#include <cuda_runtime.h>
#include <cuda_fp16.h>
#include <cstdint>
#include <cstddef>

#define TOKENS 8192
#define DIN    4096
#define DOUT   16384

// ---------------- device scratch (static: no runtime allocation) ----------------
// Packed fp16 layouts: 128row x 64col blocks (16 KB, 128B rows), SW128-swizzled.
// g_Xh: block(mt, kt) at ((mt*64 + kt) * 16384)   [mt: 64, kt: 64]   64 MB
// g_Wh: block(nt, kt) at ((nt*64 + kt) * 16384)   [nt: 128, kt: 64] 128 MB
static __device__ uint8_t g_Xh[(size_t)TOKENS * DIN * 2];
static __device__ uint8_t g_Wh[(size_t)DOUT   * DIN * 2];

// ---------------- PTX helpers ----------------
__device__ __forceinline__ uint32_t smem_u32(const void* p) {
    uint32_t a;
    asm("{ .reg .u64 t; cvta.to.shared.u64 t, %1; cvt.u32.u64 %0, t; }" : "=r"(a) : "l"(p));
    return a;
}
__device__ __forceinline__ void bulk_cp(uint32_t dst, const void* src, uint32_t bytes,
                                        uint32_t mbar) {
    asm volatile(
        "cp.async.bulk.shared::cluster.global.mbarrier::complete_tx::bytes [%0], [%1], %2, [%3];"
        :: "r"(dst), "l"(src), "r"(bytes), "r"(mbar) : "memory");
}
__device__ __forceinline__ void expect_tx(uint32_t mbar, uint32_t bytes) {
    asm volatile("mbarrier.arrive.expect_tx.shared.b64 _, [%0], %1;"
                 :: "r"(mbar), "r"(bytes) : "memory");
}
__device__ __forceinline__ void mbar_init(uint32_t addr, uint32_t cnt) {
    asm volatile("mbarrier.init.shared.b64 [%0], %1;" :: "r"(addr), "r"(cnt) : "memory");
}
__device__ __forceinline__ void mbar_wait(uint32_t addr, uint32_t parity) {
    asm volatile(
        "{\n\t.reg .pred P;\n\t"
        "LAB_WAIT_%=:\n\t"
        "mbarrier.try_wait.parity.acquire.cta.shared::cta.b64 P, [%0], %1, 0x989680;\n\t"
        "@P bra.uni LAB_DONE_%=;\n\t"
        "bra.uni LAB_WAIT_%=;\n\t"
        "LAB_DONE_%=:\n\t}"
        :: "r"(addr), "r"(parity) : "memory");
}
__device__ __forceinline__ void ldsm4(uint32_t& r0, uint32_t& r1, uint32_t& r2, uint32_t& r3,
                                      uint32_t addr) {
    asm volatile("ldmatrix.sync.aligned.m8n8.x4.shared.b16 {%0,%1,%2,%3}, [%4];"
                 : "=r"(r0), "=r"(r1), "=r"(r2), "=r"(r3) : "r"(addr));
}
__device__ __forceinline__ void hmma16816(float* d, const uint32_t* a, const uint32_t* b) {
    asm volatile(
        "mma.sync.aligned.m16n8k16.row.col.f32.f16.f16.f32 "
        "{%0,%1,%2,%3}, {%4,%5,%6,%7}, {%8,%9}, {%0,%1,%2,%3};"
        : "+f"(d[0]), "+f"(d[1]), "+f"(d[2]), "+f"(d[3])
        : "r"(a[0]), "r"(a[1]), "r"(a[2]), "r"(a[3]), "r"(b[0]), "r"(b[1]));
}

// ---------------- convert kernels (write packed + swizzled fp16) ----------------
__global__ void __launch_bounds__(256) convert_w_kernel(const int* __restrict__ q) {
    size_t i = (size_t)blockIdx.x * 256 + threadIdx.x;   // int4 index (4 ints)
    int4 v = ((const int4*)q)[i];
    const int n  = (int)(i >> 10);            // DIN/4 = 1024 int4 per row
    const int k  = ((int)i & 1023) * 4;
    const int nt = n >> 7, r = n & 127, kt = k >> 6, c = k & 63;
    const size_t blk = ((size_t)nt * 64 + kt) * 16384;
    const uint32_t off = (uint32_t)(r * 128 + ((2 * c) ^ ((r & 7) << 4)));
    __half2 h0 = __halves2half2(__int2half_rn(v.x), __int2half_rn(v.y));
    __half2 h1 = __halves2half2(__int2half_rn(v.z), __int2half_rn(v.w));
    uint2 o;
    o.x = *(uint32_t*)&h0;
    o.y = *(uint32_t*)&h1;
    *(uint2*)(g_Wh + blk + off) = o;
}

__global__ void __launch_bounds__(256) convert_x_kernel(const float* __restrict__ x) {
    size_t i = (size_t)blockIdx.x * 256 + threadIdx.x;   // float4 index
    float4 v = ((const float4*)x)[i];
    const int t  = (int)(i >> 10);
    const int k  = ((int)i & 1023) * 4;
    const int mt = t >> 7, r = t & 127, kt = k >> 6, c = k & 63;
    const size_t blk = ((size_t)mt * 64 + kt) * 16384;
    const uint32_t off = (uint32_t)(r * 128 + ((2 * c) ^ ((r & 7) << 4)));
    __half2 h0 = __floats2half2_rn(v.x, v.y);
    __half2 h1 = __floats2half2_rn(v.z, v.w);
    uint2 o;
    o.x = *(uint32_t*)&h0;
    o.y = *(uint32_t*)&h1;
    *(uint2*)(g_Xh + blk + off) = o;
}

// ---------------- GEMM ----------------
// Single fp16 GEMM, fp32 accum. CTA tile 128(M) x 128(N), K-tile 128 (2 blocks).
// 512 threads = 16 warps (4 row-bands x 4 col-bands), warp tile 32x32.
// Stage = A(2x16K) + B(2x16K) = 64KB; 3 stages; TWO 32KB bulk copies per stage.
static constexpr int STAGE_BYTES = 65536;
static constexpr int STAGES      = 3;
static constexpr int MBAR_OFF    = STAGES * STAGE_BYTES;       // 196608
static constexpr int SMEM_BYTES  = MBAR_OFF + 64;              // 196672
static constexpr int KTILES      = DIN / 128;                  // 32

__global__ void __launch_bounds__(512, 1)
qlinear_gemm(const int* __restrict__ q_bias, const float* __restrict__ scale,
             const float* __restrict__ bias_scale, float* __restrict__ out,
             int m_base)
{
    extern __shared__ char smem[];
    const uint32_t sb = smem_u32(smem);
    const int tid  = threadIdx.x;
    const int wid  = tid >> 5;
    const int lane = tid & 31;
    const int wrow = wid >> 2;            // 0..3 : rows 32*wrow..+31
    const int wcol = wid & 3;             // 0..3 : cols 32*wcol..+31

    // rasterization: 8 m-tiles per group (launch covers 16 m-tiles x 128 n-tiles)
    const int bid    = blockIdx.x;
    const int group  = bid >> 10;
    const int m_tile = (m_base >> 7) + (group << 3) + (bid & 7);
    const int n_tile = (bid >> 3) & 127;
    const int m0     = m_tile * 128;
    const int n0     = n_tile * 128;

    if (tid == 0) {
#pragma unroll
        for (int s = 0; s < STAGES; ++s) mbar_init(sb + MBAR_OFF + s * 8, 1);
    }
    __syncthreads();

    const uint8_t* a_src = g_Xh + (size_t)m_tile * 64 * 16384;   // 1 MB per m-tile
    const uint8_t* w_src = g_Wh + (size_t)n_tile * 64 * 16384;   // 1 MB per n-tile

    // prologue: fill stages 0,1
    if (tid == 0) {
#pragma unroll
        for (int s = 0; s < 2; ++s) {
            const uint32_t mb  = sb + MBAR_OFF + s * 8;
            const uint32_t dst = sb + s * STAGE_BYTES;
            expect_tx(mb, STAGE_BYTES);
            bulk_cp(dst,         a_src + (size_t)s * 32768, 32768, mb);
            bulk_cp(dst + 32768, w_src + (size_t)s * 32768, 32768, mb);
        }
    }

    // per-lane operand addressing (swizzle folded into k-byte XOR)
    const int arow = wrow * 32 + (lane & 15);
    const uint32_t aBase = (uint32_t)arow * 128;               // mt=1 adds 2048
    const uint32_t axor  = (uint32_t)((arow & 7) << 4);
    const int brow = wcol * 32 + ((lane >> 4) << 3) + (lane & 7);
    const uint32_t bBase = 32768u + (uint32_t)brow * 128;      // second ldsm +2048
    const uint32_t bxor  = (uint32_t)((brow & 7) << 4);
    uint32_t aoff[8], boff[8];
#pragma unroll
    for (int ks = 0; ks < 8; ++ks) {
        const uint32_t kblk = (uint32_t)(ks >> 2) * 16384;
        aoff[ks] = kblk + ((((ks & 3) * 32) + ((lane >> 4) * 16)) ^ axor);
        boff[ks] = kblk + ((((ks & 3) * 32) + (((lane >> 3) & 1) * 16)) ^ bxor);
    }

    float acc[2][4][4] = {};
    int cph = 0;

#pragma unroll 1
    for (int i = 0; i < KTILES; ++i) {
        const int cbuf = i % 3;
        __syncthreads();                              // buf (i+2)%3 fully consumed
        const int nxt = i + 2;
        if (nxt < KTILES && tid == 0) {
            const int pb = nxt % 3;
            const uint32_t mb  = sb + MBAR_OFF + pb * 8;
            const uint32_t dst = sb + pb * STAGE_BYTES;
            expect_tx(mb, STAGE_BYTES);
            bulk_cp(dst,         a_src + (size_t)nxt * 32768, 32768, mb);
            bulk_cp(dst + 32768, w_src + (size_t)nxt * 32768, 32768, mb);
        }
        mbar_wait(sb + MBAR_OFF + cbuf * 8, cph);
        if (cbuf == 2) cph ^= 1;

        const uint32_t stg = sb + (uint32_t)cbuf * STAGE_BYTES;
#pragma unroll
        for (int ks = 0; ks < 8; ++ks) {
            uint32_t b[4][2];
            // sequential pairing (proven in R7): first ldsm = band rows 0-15
            ldsm4(b[0][0], b[0][1], b[1][0], b[1][1], stg + bBase + boff[ks]);
            ldsm4(b[2][0], b[2][1], b[3][0], b[3][1], stg + bBase + 2048 + boff[ks]);
#pragma unroll
            for (int mt = 0; mt < 2; ++mt) {
                uint32_t a[4];
                ldsm4(a[0], a[1], a[2], a[3], stg + aBase + mt * 2048 + aoff[ks]);
                hmma16816(acc[mt][0], a, b[0]);
                hmma16816(acc[mt][1], a, b[1]);
                hmma16816(acc[mt][2], a, b[2]);
                hmma16816(acc[mt][3], a, b[3]);
            }
        }
    }

    // ---------------- epilogue: out = sc*acc + bias, direct stores ----------------
    const float sc  = scale[0];
    const float bsc = bias_scale[0];
    const int r  = lane >> 2;             // 0..7
    const int kg = lane & 3;              // 0..3

#pragma unroll
    for (int nt = 0; nt < 4; ++nt) {
        const int col = wcol * 32 + nt * 8 + kg * 2;
        const int2 qb = *(const int2*)(q_bias + n0 + col);
        const float b0 = qb.x * bsc, b1 = qb.y * bsc;
#pragma unroll
        for (int mt = 0; mt < 2; ++mt) {
            const int row = wrow * 32 + mt * 16 + r;
            float2 r0, r1;
            r0.x = sc * acc[mt][nt][0] + b0;
            r0.y = sc * acc[mt][nt][1] + b1;
            r1.x = sc * acc[mt][nt][2] + b0;
            r1.y = sc * acc[mt][nt][3] + b1;
            *(float2*)(out + (size_t)(m0 + row)     * DOUT + n0 + col) = r0;
            *(float2*)(out + (size_t)(m0 + row + 8) * DOUT + n0 + col) = r1;
        }
    }
}

// ---------------- launch ----------------
extern "C" void kernel_launch(void* const* d_in, const int* in_sizes, int n_in,
                              void* d_out, int out_size) {
    const float* x   = (const float*)d_in[0];
    const int*   qw  = (const int*)d_in[1];
    const int*   qb  = (const int*)d_in[2];
    const float* sc  = (const float*)d_in[3];
    const float* bsc = (const float*)d_in[4];
    float* out = (float*)d_out;

    cudaFuncSetAttribute(qlinear_gemm, cudaFuncAttributeMaxDynamicSharedMemorySize, SMEM_BYTES);

    convert_w_kernel<<<(DOUT * (size_t)DIN) / 4 / 256, 256>>>(qw);   // 65536 blocks
    convert_x_kernel<<<(TOKENS * (size_t)DIN) / 4 / 256, 256>>>(x);  // 32768 blocks
    // GEMM split into 4 M-chunks (2048 tokens each) so ncu (-s 5 -c 1) lands on it.
    for (int c = 0; c < 4; ++c)
        qlinear_gemm<<<16 * 128, 512, SMEM_BYTES>>>(qb, sc, bsc, out, c * 2048);
}

// round 9
// speedup vs baseline: 7.3460x; 1.0983x over previous
#include <cuda_runtime.h>
#include <cuda_fp16.h>
#include <cstdint>
#include <cstddef>

#define TOKENS 8192
#define DIN    4096
#define DOUT   16384

// ---------------- device scratch (static: no runtime allocation) ----------------
// Packed fp16 layouts: 128row x 64col blocks (16 KB, 128B rows), SW128-swizzled.
// g_Xh: block(mt, kt) at ((mt*64 + kt) * 16384)   [mt: 64, kt: 64]   64 MB
// g_Wh: block(nt, kt) at ((nt*64 + kt) * 16384)   [nt: 128, kt: 64] 128 MB
static __device__ uint8_t g_Xh[(size_t)TOKENS * DIN * 2];
static __device__ uint8_t g_Wh[(size_t)DOUT   * DIN * 2];

// ---------------- PTX helpers ----------------
__device__ __forceinline__ uint32_t smem_u32(const void* p) {
    uint32_t a;
    asm("{ .reg .u64 t; cvta.to.shared.u64 t, %1; cvt.u32.u64 %0, t; }" : "=r"(a) : "l"(p));
    return a;
}
__device__ __forceinline__ void bulk_cp(uint32_t dst, const void* src, uint32_t bytes,
                                        uint32_t mbar) {
    asm volatile(
        "cp.async.bulk.shared::cluster.global.mbarrier::complete_tx::bytes [%0], [%1], %2, [%3];"
        :: "r"(dst), "l"(src), "r"(bytes), "r"(mbar) : "memory");
}
__device__ __forceinline__ void expect_tx(uint32_t mbar, uint32_t bytes) {
    asm volatile("mbarrier.arrive.expect_tx.shared.b64 _, [%0], %1;"
                 :: "r"(mbar), "r"(bytes) : "memory");
}
__device__ __forceinline__ void mbar_init(uint32_t addr, uint32_t cnt) {
    asm volatile("mbarrier.init.shared.b64 [%0], %1;" :: "r"(addr), "r"(cnt) : "memory");
}
__device__ __forceinline__ void mbar_wait(uint32_t addr, uint32_t parity) {
    asm volatile(
        "{\n\t.reg .pred P;\n\t"
        "LAB_WAIT_%=:\n\t"
        "mbarrier.try_wait.parity.acquire.cta.shared::cta.b64 P, [%0], %1, 0x989680;\n\t"
        "@P bra.uni LAB_DONE_%=;\n\t"
        "bra.uni LAB_WAIT_%=;\n\t"
        "LAB_DONE_%=:\n\t}"
        :: "r"(addr), "r"(parity) : "memory");
}
__device__ __forceinline__ void ldsm4(uint32_t& r0, uint32_t& r1, uint32_t& r2, uint32_t& r3,
                                      uint32_t addr) {
    asm volatile("ldmatrix.sync.aligned.m8n8.x4.shared.b16 {%0,%1,%2,%3}, [%4];"
                 : "=r"(r0), "=r"(r1), "=r"(r2), "=r"(r3) : "r"(addr));
}
__device__ __forceinline__ void hmma16816(float* d, const uint32_t* a, const uint32_t* b) {
    asm volatile(
        "mma.sync.aligned.m16n8k16.row.col.f32.f16.f16.f32 "
        "{%0,%1,%2,%3}, {%4,%5,%6,%7}, {%8,%9}, {%0,%1,%2,%3};"
        : "+f"(d[0]), "+f"(d[1]), "+f"(d[2]), "+f"(d[3])
        : "r"(a[0]), "r"(a[1]), "r"(a[2]), "r"(a[3]), "r"(b[0]), "r"(b[1]));
}

// ---------------- convert kernels (write packed + swizzled fp16) ----------------
__global__ void __launch_bounds__(256) convert_w_kernel(const int* __restrict__ q) {
    size_t i = (size_t)blockIdx.x * 256 + threadIdx.x;   // int4 index (4 ints)
    int4 v = ((const int4*)q)[i];
    const int n  = (int)(i >> 10);            // DIN/4 = 1024 int4 per row
    const int k  = ((int)i & 1023) * 4;
    const int nt = n >> 7, r = n & 127, kt = k >> 6, c = k & 63;
    const size_t blk = ((size_t)nt * 64 + kt) * 16384;
    const uint32_t off = (uint32_t)(r * 128 + ((2 * c) ^ ((r & 7) << 4)));
    __half2 h0 = __halves2half2(__int2half_rn(v.x), __int2half_rn(v.y));
    __half2 h1 = __halves2half2(__int2half_rn(v.z), __int2half_rn(v.w));
    uint2 o;
    o.x = *(uint32_t*)&h0;
    o.y = *(uint32_t*)&h1;
    *(uint2*)(g_Wh + blk + off) = o;
}

__global__ void __launch_bounds__(256) convert_x_kernel(const float* __restrict__ x) {
    size_t i = (size_t)blockIdx.x * 256 + threadIdx.x;   // float4 index
    float4 v = ((const float4*)x)[i];
    const int t  = (int)(i >> 10);
    const int k  = ((int)i & 1023) * 4;
    const int mt = t >> 7, r = t & 127, kt = k >> 6, c = k & 63;
    const size_t blk = ((size_t)mt * 64 + kt) * 16384;
    const uint32_t off = (uint32_t)(r * 128 + ((2 * c) ^ ((r & 7) << 4)));
    __half2 h0 = __floats2half2_rn(v.x, v.y);
    __half2 h1 = __floats2half2_rn(v.z, v.w);
    uint2 o;
    o.x = *(uint32_t*)&h0;
    o.y = *(uint32_t*)&h1;
    *(uint2*)(g_Xh + blk + off) = o;
}

// ---------------- GEMM ----------------
// fp16 GEMM, fp32 accum. CTA tile 256(M) x 128(N), K-tile 64, 64 iters.
// 512 threads = 16 warps (4 row-bands of 64 x 4 col-bands of 32), warp tile 64x32.
// A frag reused over 4 nt, B frag over 4 mt: 192B SMEM read per HMMA (was 256B).
// Stage = A(2x16K) + B(16K) = 48KB; 4 stages (192KB); THREE 16KB bulk copies.
static constexpr int STAGE_BYTES = 49152;
static constexpr int STAGES      = 4;
static constexpr int MBAR_OFF    = STAGES * STAGE_BYTES;       // 196608
static constexpr int SMEM_BYTES  = MBAR_OFF + 64;              // 196672
static constexpr int KTILES      = DIN / 64;                   // 64

__global__ void __launch_bounds__(512, 1)
qlinear_gemm(const int* __restrict__ q_bias, const float* __restrict__ scale,
             const float* __restrict__ bias_scale, float* __restrict__ out,
             int m_base)
{
    extern __shared__ char smem[];
    const uint32_t sb = smem_u32(smem);
    const int tid  = threadIdx.x;
    const int wid  = tid >> 5;
    const int lane = tid & 31;
    const int wrow = wid >> 2;            // 0..3 : rows 64*wrow..+63 (of 256)
    const int wcol = wid & 3;             // 0..3 : cols 32*wcol..+31

    // launch covers 8 m2-tiles (256 rows each) x 128 n-tiles = 1024 CTAs
    const int bid     = blockIdx.x;
    const int m_tile2 = (m_base >> 8) + (bid & 7);
    const int n_tile  = bid >> 3;
    const int m0      = m_tile2 * 256;
    const int n0      = n_tile * 128;

    if (tid == 0) {
#pragma unroll
        for (int s = 0; s < STAGES; ++s) mbar_init(sb + MBAR_OFF + s * 8, 1);
    }
    __syncthreads();

    // block sources: A needs two 128-row block columns (not contiguous), B one.
    const uint8_t* a0src = g_Xh + ((size_t)(2 * m_tile2)     * 64) * 16384;
    const uint8_t* a1src = g_Xh + ((size_t)(2 * m_tile2 + 1) * 64) * 16384;
    const uint8_t* w_src = g_Wh + ((size_t)n_tile * 64) * 16384;

    // prologue: fill stages 0..2
    if (tid == 0) {
#pragma unroll
        for (int s = 0; s < 3; ++s) {
            const uint32_t mb  = sb + MBAR_OFF + s * 8;
            const uint32_t dst = sb + s * STAGE_BYTES;
            expect_tx(mb, STAGE_BYTES);
            bulk_cp(dst,         a0src + (size_t)s * 16384, 16384, mb);
            bulk_cp(dst + 16384, a1src + (size_t)s * 16384, 16384, mb);
            bulk_cp(dst + 32768, w_src + (size_t)s * 16384, 16384, mb);
        }
    }

    // per-lane operand addressing (swizzle folded into k-byte XOR)
    const int arow = wrow * 64 + (lane & 15);                  // 0..255
    const uint32_t aBase = (uint32_t)((arow >> 7) * 16384 + (arow & 127) * 128);
    const uint32_t axor  = (uint32_t)((arow & 7) << 4);
    const int brow = wcol * 32 + ((lane >> 4) << 3) + (lane & 7);
    const uint32_t bBase = 32768u + (uint32_t)brow * 128;      // second ldsm +2048
    const uint32_t bxor  = (uint32_t)((brow & 7) << 4);
    uint32_t aoff[4], boff[4];
#pragma unroll
    for (int ks = 0; ks < 4; ++ks) {
        aoff[ks] = ((uint32_t)(ks * 32) + (uint32_t)((lane >> 4) * 16)) ^ axor;
        boff[ks] = ((uint32_t)(ks * 32) + (uint32_t)(((lane >> 3) & 1) * 16)) ^ bxor;
    }

    float acc[4][4][4] = {};
    int cph = 0;

#pragma unroll 1
    for (int i = 0; i < KTILES; ++i) {
        const int cbuf = i & 3;
        __syncthreads();                              // buf (i+3)&3 fully consumed
        const int nxt = i + 3;
        if (nxt < KTILES && tid == 0) {
            const int pb = nxt & 3;
            const uint32_t mb  = sb + MBAR_OFF + pb * 8;
            const uint32_t dst = sb + pb * STAGE_BYTES;
            expect_tx(mb, STAGE_BYTES);
            bulk_cp(dst,         a0src + (size_t)nxt * 16384, 16384, mb);
            bulk_cp(dst + 16384, a1src + (size_t)nxt * 16384, 16384, mb);
            bulk_cp(dst + 32768, w_src + (size_t)nxt * 16384, 16384, mb);
        }
        mbar_wait(sb + MBAR_OFF + cbuf * 8, cph);
        if (cbuf == 3) cph ^= 1;

        const uint32_t stg = sb + (uint32_t)cbuf * STAGE_BYTES;
#pragma unroll
        for (int ks = 0; ks < 4; ++ks) {
            uint32_t b[4][2];
            // sequential pairing (proven): first ldsm = band rows 0-15
            ldsm4(b[0][0], b[0][1], b[1][0], b[1][1], stg + bBase + boff[ks]);
            ldsm4(b[2][0], b[2][1], b[3][0], b[3][1], stg + bBase + 2048 + boff[ks]);
#pragma unroll
            for (int mt = 0; mt < 4; ++mt) {
                uint32_t a[4];
                ldsm4(a[0], a[1], a[2], a[3], stg + aBase + mt * 2048 + aoff[ks]);
                hmma16816(acc[mt][0], a, b[0]);
                hmma16816(acc[mt][1], a, b[1]);
                hmma16816(acc[mt][2], a, b[2]);
                hmma16816(acc[mt][3], a, b[3]);
            }
        }
    }

    // ---------------- epilogue: out = sc*acc + bias, direct stores ----------------
    const float sc  = scale[0];
    const float bsc = bias_scale[0];
    const int r  = lane >> 2;             // 0..7
    const int kg = lane & 3;              // 0..3

#pragma unroll
    for (int nt = 0; nt < 4; ++nt) {
        const int col = wcol * 32 + nt * 8 + kg * 2;
        const int2 qb = *(const int2*)(q_bias + n0 + col);
        const float b0 = qb.x * bsc, b1 = qb.y * bsc;
#pragma unroll
        for (int mt = 0; mt < 4; ++mt) {
            const int row = wrow * 64 + mt * 16 + r;
            float2 r0, r1;
            r0.x = sc * acc[mt][nt][0] + b0;
            r0.y = sc * acc[mt][nt][1] + b1;
            r1.x = sc * acc[mt][nt][2] + b0;
            r1.y = sc * acc[mt][nt][3] + b1;
            *(float2*)(out + (size_t)(m0 + row)     * DOUT + n0 + col) = r0;
            *(float2*)(out + (size_t)(m0 + row + 8) * DOUT + n0 + col) = r1;
        }
    }
}

// ---------------- launch ----------------
extern "C" void kernel_launch(void* const* d_in, const int* in_sizes, int n_in,
                              void* d_out, int out_size) {
    const float* x   = (const float*)d_in[0];
    const int*   qw  = (const int*)d_in[1];
    const int*   qb  = (const int*)d_in[2];
    const float* sc  = (const float*)d_in[3];
    const float* bsc = (const float*)d_in[4];
    float* out = (float*)d_out;

    cudaFuncSetAttribute(qlinear_gemm, cudaFuncAttributeMaxDynamicSharedMemorySize, SMEM_BYTES);

    convert_w_kernel<<<(DOUT * (size_t)DIN) / 4 / 256, 256>>>(qw);   // 65536 blocks
    convert_x_kernel<<<(TOKENS * (size_t)DIN) / 4 / 256, 256>>>(x);  // 32768 blocks
    // GEMM split into 4 M-chunks (2048 tokens each) so ncu (-s 5 -c 1) lands on it.
    for (int c = 0; c < 4; ++c)
        qlinear_gemm<<<8 * 128, 512, SMEM_BYTES>>>(qb, sc, bsc, out, c * 2048);
}

// round 10
// speedup vs baseline: 8.3021x; 1.1301x over previous
#include <cuda_runtime.h>
#include <cuda_fp16.h>
#include <cstdint>
#include <cstddef>

#define TOKENS 8192
#define DIN    4096
#define DOUT   16384

// ---------------- device scratch (static: no runtime allocation) ----------------
// Packed fp16 layouts: 128row x 64col blocks (16 KB, 128B rows), SW128-swizzled.
// g_Xh: block(mt, kt) at ((mt*64 + kt) * 16384)   [mt: 64, kt: 64]   64 MB
// g_Wh: block(nt, kt) at ((nt*64 + kt) * 16384)   [nt: 128, kt: 64] 128 MB
static __device__ uint8_t g_Xh[(size_t)TOKENS * DIN * 2];
static __device__ uint8_t g_Wh[(size_t)DOUT   * DIN * 2];

// ---------------- PTX helpers ----------------
__device__ __forceinline__ uint32_t smem_u32(const void* p) {
    uint32_t a;
    asm("{ .reg .u64 t; cvta.to.shared.u64 t, %1; cvt.u32.u64 %0, t; }" : "=r"(a) : "l"(p));
    return a;
}
__device__ __forceinline__ void bulk_cp(uint32_t dst, const void* src, uint32_t bytes,
                                        uint32_t mbar) {
    asm volatile(
        "cp.async.bulk.shared::cluster.global.mbarrier::complete_tx::bytes [%0], [%1], %2, [%3];"
        :: "r"(dst), "l"(src), "r"(bytes), "r"(mbar) : "memory");
}
__device__ __forceinline__ void expect_tx(uint32_t mbar, uint32_t bytes) {
    asm volatile("mbarrier.arrive.expect_tx.shared.b64 _, [%0], %1;"
                 :: "r"(mbar), "r"(bytes) : "memory");
}
__device__ __forceinline__ void mbar_arrive(uint32_t mbar) {
    asm volatile("mbarrier.arrive.release.cta.shared.b64 _, [%0];" :: "r"(mbar) : "memory");
}
__device__ __forceinline__ void mbar_init(uint32_t addr, uint32_t cnt) {
    asm volatile("mbarrier.init.shared.b64 [%0], %1;" :: "r"(addr), "r"(cnt) : "memory");
}
__device__ __forceinline__ void mbar_wait(uint32_t addr, uint32_t parity) {
    asm volatile(
        "{\n\t.reg .pred P;\n\t"
        "LAB_WAIT_%=:\n\t"
        "mbarrier.try_wait.parity.acquire.cta.shared::cta.b64 P, [%0], %1, 0x989680;\n\t"
        "@P bra.uni LAB_DONE_%=;\n\t"
        "bra.uni LAB_WAIT_%=;\n\t"
        "LAB_DONE_%=:\n\t}"
        :: "r"(addr), "r"(parity) : "memory");
}
__device__ __forceinline__ void ldsm4(uint32_t& r0, uint32_t& r1, uint32_t& r2, uint32_t& r3,
                                      uint32_t addr) {
    asm volatile("ldmatrix.sync.aligned.m8n8.x4.shared.b16 {%0,%1,%2,%3}, [%4];"
                 : "=r"(r0), "=r"(r1), "=r"(r2), "=r"(r3) : "r"(addr));
}
__device__ __forceinline__ void hmma16816(float* d, const uint32_t* a, const uint32_t* b) {
    asm volatile(
        "mma.sync.aligned.m16n8k16.row.col.f32.f16.f16.f32 "
        "{%0,%1,%2,%3}, {%4,%5,%6,%7}, {%8,%9}, {%0,%1,%2,%3};"
        : "+f"(d[0]), "+f"(d[1]), "+f"(d[2]), "+f"(d[3])
        : "r"(a[0]), "r"(a[1]), "r"(a[2]), "r"(a[3]), "r"(b[0]), "r"(b[1]));
}

// ---------------- convert kernels (write packed + swizzled fp16) ----------------
__global__ void __launch_bounds__(256) convert_w_kernel(const int* __restrict__ q) {
    size_t i = (size_t)blockIdx.x * 256 + threadIdx.x;   // int4 index (4 ints)
    int4 v = ((const int4*)q)[i];
    const int n  = (int)(i >> 10);            // DIN/4 = 1024 int4 per row
    const int k  = ((int)i & 1023) * 4;
    const int nt = n >> 7, r = n & 127, kt = k >> 6, c = k & 63;
    const size_t blk = ((size_t)nt * 64 + kt) * 16384;
    const uint32_t off = (uint32_t)(r * 128 + ((2 * c) ^ ((r & 7) << 4)));
    __half2 h0 = __halves2half2(__int2half_rn(v.x), __int2half_rn(v.y));
    __half2 h1 = __halves2half2(__int2half_rn(v.z), __int2half_rn(v.w));
    uint2 o;
    o.x = *(uint32_t*)&h0;
    o.y = *(uint32_t*)&h1;
    *(uint2*)(g_Wh + blk + off) = o;
}

__global__ void __launch_bounds__(256) convert_x_kernel(const float* __restrict__ x) {
    size_t i = (size_t)blockIdx.x * 256 + threadIdx.x;   // float4 index
    float4 v = ((const float4*)x)[i];
    const int t  = (int)(i >> 10);
    const int k  = ((int)i & 1023) * 4;
    const int mt = t >> 7, r = t & 127, kt = k >> 6, c = k & 63;
    const size_t blk = ((size_t)mt * 64 + kt) * 16384;
    const uint32_t off = (uint32_t)(r * 128 + ((2 * c) ^ ((r & 7) << 4)));
    __half2 h0 = __floats2half2_rn(v.x, v.y);
    __half2 h1 = __floats2half2_rn(v.z, v.w);
    uint2 o;
    o.x = *(uint32_t*)&h0;
    o.y = *(uint32_t*)&h1;
    *(uint2*)(g_Xh + blk + off) = o;
}

// ---------------- GEMM ----------------
// fp16 GEMM, fp32 accum. CTA tile 256(M) x 128(N), K-tile 64, 64 iters.
// 512 threads = 16 warps (4 row-bands of 64 x 4 col-bands of 32), warp tile 64x32.
// NO __syncthreads in mainloop: full/empty mbarrier pairs, warps free-run.
// Stage = A(2x16K) + B(16K) = 48KB; 4 stages (192KB); THREE 16KB bulk copies.
static constexpr int STAGE_BYTES = 49152;
static constexpr int STAGES      = 4;
static constexpr int FULL_OFF    = STAGES * STAGE_BYTES;       // 196608
static constexpr int EMPTY_OFF   = FULL_OFF + STAGES * 8;      // 196640
static constexpr int SMEM_BYTES  = EMPTY_OFF + STAGES * 8;     // 196672
static constexpr int KTILES      = DIN / 64;                   // 64

__global__ void __launch_bounds__(512, 1)
qlinear_gemm(const int* __restrict__ q_bias, const float* __restrict__ scale,
             const float* __restrict__ bias_scale, float* __restrict__ out,
             int m_base)
{
    extern __shared__ char smem[];
    const uint32_t sb = smem_u32(smem);
    const int tid  = threadIdx.x;
    const int wid  = tid >> 5;
    const int lane = tid & 31;
    const int wrow = wid >> 2;            // 0..3 : rows 64*wrow..+63 (of 256)
    const int wcol = wid & 3;             // 0..3 : cols 32*wcol..+31

    // launch covers 8 m2-tiles (256 rows each) x 128 n-tiles = 1024 CTAs
    const int bid     = blockIdx.x;
    const int m_tile2 = (m_base >> 8) + (bid & 7);
    const int n_tile  = bid >> 3;
    const int m0      = m_tile2 * 256;
    const int n0      = n_tile * 128;

    if (tid == 0) {
#pragma unroll
        for (int s = 0; s < STAGES; ++s) {
            mbar_init(sb + FULL_OFF + s * 8, 1);     // tx-based
            mbar_init(sb + EMPTY_OFF + s * 8, 16);   // one lane per warp
        }
    }
    __syncthreads();

    // block sources: A needs two 128-row block columns (not contiguous), B one.
    const uint8_t* a0src = g_Xh + ((size_t)(2 * m_tile2)     * 64) * 16384;
    const uint8_t* a1src = g_Xh + ((size_t)(2 * m_tile2 + 1) * 64) * 16384;
    const uint8_t* w_src = g_Wh + ((size_t)n_tile * 64) * 16384;

    // prologue: fill stages 0..2 (buffers fresh, no empty-wait needed)
    if (tid == 0) {
#pragma unroll
        for (int s = 0; s < 3; ++s) {
            const uint32_t mb  = sb + FULL_OFF + s * 8;
            const uint32_t dst = sb + s * STAGE_BYTES;
            expect_tx(mb, STAGE_BYTES);
            bulk_cp(dst,         a0src + (size_t)s * 16384, 16384, mb);
            bulk_cp(dst + 16384, a1src + (size_t)s * 16384, 16384, mb);
            bulk_cp(dst + 32768, w_src + (size_t)s * 16384, 16384, mb);
        }
    }

    // per-lane operand addressing (swizzle folded into k-byte XOR)
    const int arow = wrow * 64 + (lane & 15);                  // 0..255
    const uint32_t aBase = (uint32_t)((arow >> 7) * 16384 + (arow & 127) * 128);
    const uint32_t axor  = (uint32_t)((arow & 7) << 4);
    const int brow = wcol * 32 + ((lane >> 4) << 3) + (lane & 7);
    const uint32_t bBase = 32768u + (uint32_t)brow * 128;      // second ldsm +2048
    const uint32_t bxor  = (uint32_t)((brow & 7) << 4);
    uint32_t aoff[4], boff[4];
#pragma unroll
    for (int ks = 0; ks < 4; ++ks) {
        aoff[ks] = ((uint32_t)(ks * 32) + (uint32_t)((lane >> 4) * 16)) ^ axor;
        boff[ks] = ((uint32_t)(ks * 32) + (uint32_t)(((lane >> 3) & 1) * 16)) ^ bxor;
    }

    float acc[4][4][4] = {};

#pragma unroll 1
    for (int i = 0; i < KTILES; ++i) {
        const int cbuf = i & 3;
        const int nxt = i + 3;
        if (nxt < KTILES && tid == 0) {
            const int pb = nxt & 3;
            // buffer pb was last consumed at iter nxt-4; first fills (nxt<4) skip wait
            if (nxt >= 4) mbar_wait(sb + EMPTY_OFF + pb * 8, ((nxt >> 2) - 1) & 1);
            const uint32_t mb  = sb + FULL_OFF + pb * 8;
            const uint32_t dst = sb + pb * STAGE_BYTES;
            expect_tx(mb, STAGE_BYTES);
            bulk_cp(dst,         a0src + (size_t)nxt * 16384, 16384, mb);
            bulk_cp(dst + 16384, a1src + (size_t)nxt * 16384, 16384, mb);
            bulk_cp(dst + 32768, w_src + (size_t)nxt * 16384, 16384, mb);
        }
        mbar_wait(sb + FULL_OFF + cbuf * 8, (i >> 2) & 1);

        const uint32_t stg = sb + (uint32_t)cbuf * STAGE_BYTES;
#pragma unroll
        for (int ks = 0; ks < 4; ++ks) {
            uint32_t b[4][2];
            // sequential pairing (proven): first ldsm = band rows 0-15
            ldsm4(b[0][0], b[0][1], b[1][0], b[1][1], stg + bBase + boff[ks]);
            ldsm4(b[2][0], b[2][1], b[3][0], b[3][1], stg + bBase + 2048 + boff[ks]);
#pragma unroll
            for (int mt = 0; mt < 4; ++mt) {
                uint32_t a[4];
                ldsm4(a[0], a[1], a[2], a[3], stg + aBase + mt * 2048 + aoff[ks]);
                hmma16816(acc[mt][0], a, b[0]);
                hmma16816(acc[mt][1], a, b[1]);
                hmma16816(acc[mt][2], a, b[2]);
                hmma16816(acc[mt][3], a, b[3]);
            }
        }
        // release buffer: one arrive per warp (ldsm reads are warp-synchronous)
        __syncwarp();
        if (lane == 0) mbar_arrive(sb + EMPTY_OFF + cbuf * 8);
    }

    // ---------------- epilogue: out = sc*acc + bias, direct stores ----------------
    const float sc  = scale[0];
    const float bsc = bias_scale[0];
    const int r  = lane >> 2;             // 0..7
    const int kg = lane & 3;              // 0..3

#pragma unroll
    for (int nt = 0; nt < 4; ++nt) {
        const int col = wcol * 32 + nt * 8 + kg * 2;
        const int2 qb = *(const int2*)(q_bias + n0 + col);
        const float b0 = qb.x * bsc, b1 = qb.y * bsc;
#pragma unroll
        for (int mt = 0; mt < 4; ++mt) {
            const int row = wrow * 64 + mt * 16 + r;
            float2 r0, r1;
            r0.x = sc * acc[mt][nt][0] + b0;
            r0.y = sc * acc[mt][nt][1] + b1;
            r1.x = sc * acc[mt][nt][2] + b0;
            r1.y = sc * acc[mt][nt][3] + b1;
            *(float2*)(out + (size_t)(m0 + row)     * DOUT + n0 + col) = r0;
            *(float2*)(out + (size_t)(m0 + row + 8) * DOUT + n0 + col) = r1;
        }
    }
}

// ---------------- launch ----------------
extern "C" void kernel_launch(void* const* d_in, const int* in_sizes, int n_in,
                              void* d_out, int out_size) {
    const float* x   = (const float*)d_in[0];
    const int*   qw  = (const int*)d_in[1];
    const int*   qb  = (const int*)d_in[2];
    const float* sc  = (const float*)d_in[3];
    const float* bsc = (const float*)d_in[4];
    float* out = (float*)d_out;

    cudaFuncSetAttribute(qlinear_gemm, cudaFuncAttributeMaxDynamicSharedMemorySize, SMEM_BYTES);

    convert_w_kernel<<<(DOUT * (size_t)DIN) / 4 / 256, 256>>>(qw);   // 65536 blocks
    convert_x_kernel<<<(TOKENS * (size_t)DIN) / 4 / 256, 256>>>(x);  // 32768 blocks
    // GEMM split into 4 M-chunks (2048 tokens each) so ncu (-s 5 -c 1) lands on it.
    for (int c = 0; c < 4; ++c)
        qlinear_gemm<<<8 * 128, 512, SMEM_BYTES>>>(qb, sc, bsc, out, c * 2048);
}

// round 11
// speedup vs baseline: 8.3023x; 1.0000x over previous
#include <cuda_runtime.h>
#include <cuda_fp16.h>
#include <cstdint>
#include <cstddef>

#define TOKENS 8192
#define DIN    4096
#define DOUT   16384

// ---------------- device scratch (static: no runtime allocation) ----------------
// Packed fp16 layouts: 128row x 64col blocks (16 KB, 128B rows), SW128-swizzled.
// g_Xh: block(mt, kt) at ((mt*64 + kt) * 16384)   [mt: 64, kt: 64]   64 MB
// g_Wh: block(nt, kt) at ((nt*64 + kt) * 16384)   [nt: 128, kt: 64] 128 MB
static __device__ uint8_t g_Xh[(size_t)TOKENS * DIN * 2];
static __device__ uint8_t g_Wh[(size_t)DOUT   * DIN * 2];

// ---------------- PTX helpers ----------------
__device__ __forceinline__ uint32_t smem_u32(const void* p) {
    uint32_t a;
    asm("{ .reg .u64 t; cvta.to.shared.u64 t, %1; cvt.u32.u64 %0, t; }" : "=r"(a) : "l"(p));
    return a;
}
__device__ __forceinline__ void bulk_cp(uint32_t dst, const void* src, uint32_t bytes,
                                        uint32_t mbar) {
    asm volatile(
        "cp.async.bulk.shared::cluster.global.mbarrier::complete_tx::bytes [%0], [%1], %2, [%3];"
        :: "r"(dst), "l"(src), "r"(bytes), "r"(mbar) : "memory");
}
__device__ __forceinline__ void expect_tx(uint32_t mbar, uint32_t bytes) {
    asm volatile("mbarrier.arrive.expect_tx.shared.b64 _, [%0], %1;"
                 :: "r"(mbar), "r"(bytes) : "memory");
}
__device__ __forceinline__ void mbar_arrive(uint32_t mbar) {
    asm volatile("mbarrier.arrive.release.cta.shared.b64 _, [%0];" :: "r"(mbar) : "memory");
}
__device__ __forceinline__ void mbar_init(uint32_t addr, uint32_t cnt) {
    asm volatile("mbarrier.init.shared.b64 [%0], %1;" :: "r"(addr), "r"(cnt) : "memory");
}
__device__ __forceinline__ void mbar_wait(uint32_t addr, uint32_t parity) {
    asm volatile(
        "{\n\t.reg .pred P;\n\t"
        "LAB_WAIT_%=:\n\t"
        "mbarrier.try_wait.parity.acquire.cta.shared::cta.b64 P, [%0], %1, 0x989680;\n\t"
        "@P bra.uni LAB_DONE_%=;\n\t"
        "bra.uni LAB_WAIT_%=;\n\t"
        "LAB_DONE_%=:\n\t}"
        :: "r"(addr), "r"(parity) : "memory");
}
__device__ __forceinline__ void ldsm4(uint32_t& r0, uint32_t& r1, uint32_t& r2, uint32_t& r3,
                                      uint32_t addr) {
    asm volatile("ldmatrix.sync.aligned.m8n8.x4.shared.b16 {%0,%1,%2,%3}, [%4];"
                 : "=r"(r0), "=r"(r1), "=r"(r2), "=r"(r3) : "r"(addr));
}
__device__ __forceinline__ void hmma16816(float* d, const uint32_t* a, const uint32_t* b) {
    asm volatile(
        "mma.sync.aligned.m16n8k16.row.col.f32.f16.f16.f32 "
        "{%0,%1,%2,%3}, {%4,%5,%6,%7}, {%8,%9}, {%0,%1,%2,%3};"
        : "+f"(d[0]), "+f"(d[1]), "+f"(d[2]), "+f"(d[3])
        : "r"(a[0]), "r"(a[1]), "r"(a[2]), "r"(a[3]), "r"(b[0]), "r"(b[1]));
}

// ---------------- convert kernels (write packed + swizzled fp16) ----------------
__global__ void __launch_bounds__(256) convert_w_kernel(const int* __restrict__ q) {
    size_t i = (size_t)blockIdx.x * 256 + threadIdx.x;   // int4 index (4 ints)
    int4 v = ((const int4*)q)[i];
    const int n  = (int)(i >> 10);            // DIN/4 = 1024 int4 per row
    const int k  = ((int)i & 1023) * 4;
    const int nt = n >> 7, r = n & 127, kt = k >> 6, c = k & 63;
    const size_t blk = ((size_t)nt * 64 + kt) * 16384;
    const uint32_t off = (uint32_t)(r * 128 + ((2 * c) ^ ((r & 7) << 4)));
    __half2 h0 = __halves2half2(__int2half_rn(v.x), __int2half_rn(v.y));
    __half2 h1 = __halves2half2(__int2half_rn(v.z), __int2half_rn(v.w));
    uint2 o;
    o.x = *(uint32_t*)&h0;
    o.y = *(uint32_t*)&h1;
    *(uint2*)(g_Wh + blk + off) = o;
}

__global__ void __launch_bounds__(256) convert_x_kernel(const float* __restrict__ x) {
    size_t i = (size_t)blockIdx.x * 256 + threadIdx.x;   // float4 index
    float4 v = ((const float4*)x)[i];
    const int t  = (int)(i >> 10);
    const int k  = ((int)i & 1023) * 4;
    const int mt = t >> 7, r = t & 127, kt = k >> 6, c = k & 63;
    const size_t blk = ((size_t)mt * 64 + kt) * 16384;
    const uint32_t off = (uint32_t)(r * 128 + ((2 * c) ^ ((r & 7) << 4)));
    __half2 h0 = __floats2half2_rn(v.x, v.y);
    __half2 h1 = __floats2half2_rn(v.z, v.w);
    uint2 o;
    o.x = *(uint32_t*)&h0;
    o.y = *(uint32_t*)&h1;
    *(uint2*)(g_Xh + blk + off) = o;
}

// ---------------- GEMM ----------------
// fp16 GEMM, fp32 accum. CTA tile 256(M) x 128(N), K-tile 64, 64 iters.
// 512 threads = 16 warps (4 row-bands of 64 x 4 col-bands of 32), warp tile 64x32.
// Free-running full/empty mbarrier pipeline. Lookahead 2 (4 buffers):
// producer at iter i refills the buffer consumed at iter i-2 -> one full
// iteration of slack, no per-iteration producer convoy (R10 had lookahead 3
// = disguised full barrier each iter).
static constexpr int STAGE_BYTES = 49152;
static constexpr int STAGES      = 4;
static constexpr int FULL_OFF    = STAGES * STAGE_BYTES;       // 196608
static constexpr int EMPTY_OFF   = FULL_OFF + STAGES * 8;      // 196640
static constexpr int SMEM_BYTES  = EMPTY_OFF + STAGES * 8;     // 196672
static constexpr int KTILES      = DIN / 64;                   // 64

__global__ void __launch_bounds__(512, 1)
qlinear_gemm(const int* __restrict__ q_bias, const float* __restrict__ scale,
             const float* __restrict__ bias_scale, float* __restrict__ out,
             int m_base)
{
    extern __shared__ char smem[];
    const uint32_t sb = smem_u32(smem);
    const int tid  = threadIdx.x;
    const int wid  = tid >> 5;
    const int lane = tid & 31;
    const int wrow = wid >> 2;            // 0..3 : rows 64*wrow..+63 (of 256)
    const int wcol = wid & 3;             // 0..3 : cols 32*wcol..+31

    // launch covers 8 m2-tiles (256 rows each) x 128 n-tiles = 1024 CTAs
    const int bid     = blockIdx.x;
    const int m_tile2 = (m_base >> 8) + (bid & 7);
    const int n_tile  = bid >> 3;
    const int m0      = m_tile2 * 256;
    const int n0      = n_tile * 128;

    if (tid == 0) {
#pragma unroll
        for (int s = 0; s < STAGES; ++s) {
            mbar_init(sb + FULL_OFF + s * 8, 1);     // tx-based
            mbar_init(sb + EMPTY_OFF + s * 8, 16);   // one lane per warp
        }
    }
    __syncthreads();

    // block sources: A needs two 128-row block columns (not contiguous), B one.
    const uint8_t* a0src = g_Xh + ((size_t)(2 * m_tile2)     * 64) * 16384;
    const uint8_t* a1src = g_Xh + ((size_t)(2 * m_tile2 + 1) * 64) * 16384;
    const uint8_t* w_src = g_Wh + ((size_t)n_tile * 64) * 16384;

    // prologue: fill stages 0,1 (lookahead 2)
    if (tid == 0) {
#pragma unroll
        for (int s = 0; s < 2; ++s) {
            const uint32_t mb  = sb + FULL_OFF + s * 8;
            const uint32_t dst = sb + s * STAGE_BYTES;
            expect_tx(mb, STAGE_BYTES);
            bulk_cp(dst,         a0src + (size_t)s * 16384, 16384, mb);
            bulk_cp(dst + 16384, a1src + (size_t)s * 16384, 16384, mb);
            bulk_cp(dst + 32768, w_src + (size_t)s * 16384, 16384, mb);
        }
    }

    // per-lane operand addressing (swizzle folded into k-byte XOR)
    const int arow = wrow * 64 + (lane & 15);                  // 0..255
    const uint32_t aBase = (uint32_t)((arow >> 7) * 16384 + (arow & 127) * 128);
    const uint32_t axor  = (uint32_t)((arow & 7) << 4);
    const int brow = wcol * 32 + ((lane >> 4) << 3) + (lane & 7);
    const uint32_t bBase = 32768u + (uint32_t)brow * 128;      // second ldsm +2048
    const uint32_t bxor  = (uint32_t)((brow & 7) << 4);
    uint32_t aoff[4], boff[4];
#pragma unroll
    for (int ks = 0; ks < 4; ++ks) {
        aoff[ks] = ((uint32_t)(ks * 32) + (uint32_t)((lane >> 4) * 16)) ^ axor;
        boff[ks] = ((uint32_t)(ks * 32) + (uint32_t)(((lane >> 3) & 1) * 16)) ^ bxor;
    }

    float acc[4][4][4] = {};

#pragma unroll 1
    for (int i = 0; i < KTILES; ++i) {
        const int cbuf = i & 3;
        const int nxt = i + 2;                        // lookahead 2
        if (nxt < KTILES && tid == 0) {
            const int pb = nxt & 3;
            // buffer pb last consumed at iter nxt-4 = i-2: one iter of slack
            if (nxt >= 4) mbar_wait(sb + EMPTY_OFF + pb * 8, ((nxt >> 2) - 1) & 1);
            const uint32_t mb  = sb + FULL_OFF + pb * 8;
            const uint32_t dst = sb + pb * STAGE_BYTES;
            expect_tx(mb, STAGE_BYTES);
            bulk_cp(dst,         a0src + (size_t)nxt * 16384, 16384, mb);
            bulk_cp(dst + 16384, a1src + (size_t)nxt * 16384, 16384, mb);
            bulk_cp(dst + 32768, w_src + (size_t)nxt * 16384, 16384, mb);
        }
        mbar_wait(sb + FULL_OFF + cbuf * 8, (i >> 2) & 1);

        const uint32_t stg = sb + (uint32_t)cbuf * STAGE_BYTES;
#pragma unroll
        for (int ks = 0; ks < 4; ++ks) {
            uint32_t b[4][2];
            // sequential pairing (proven): first ldsm = band rows 0-15
            ldsm4(b[0][0], b[0][1], b[1][0], b[1][1], stg + bBase + boff[ks]);
            ldsm4(b[2][0], b[2][1], b[3][0], b[3][1], stg + bBase + 2048 + boff[ks]);
#pragma unroll
            for (int mt = 0; mt < 4; ++mt) {
                uint32_t a[4];
                ldsm4(a[0], a[1], a[2], a[3], stg + aBase + mt * 2048 + aoff[ks]);
                hmma16816(acc[mt][0], a, b[0]);
                hmma16816(acc[mt][1], a, b[1]);
                hmma16816(acc[mt][2], a, b[2]);
                hmma16816(acc[mt][3], a, b[3]);
            }
        }
        // release buffer: one arrive per warp (ldsm reads are warp-synchronous)
        __syncwarp();
        if (lane == 0) mbar_arrive(sb + EMPTY_OFF + cbuf * 8);
    }

    // ---------------- epilogue: out = sc*acc + bias, direct stores ----------------
    const float sc  = scale[0];
    const float bsc = bias_scale[0];
    const int r  = lane >> 2;             // 0..7
    const int kg = lane & 3;              // 0..3

#pragma unroll
    for (int nt = 0; nt < 4; ++nt) {
        const int col = wcol * 32 + nt * 8 + kg * 2;
        const int2 qb = *(const int2*)(q_bias + n0 + col);
        const float b0 = qb.x * bsc, b1 = qb.y * bsc;
#pragma unroll
        for (int mt = 0; mt < 4; ++mt) {
            const int row = wrow * 64 + mt * 16 + r;
            float2 r0, r1;
            r0.x = sc * acc[mt][nt][0] + b0;
            r0.y = sc * acc[mt][nt][1] + b1;
            r1.x = sc * acc[mt][nt][2] + b0;
            r1.y = sc * acc[mt][nt][3] + b1;
            *(float2*)(out + (size_t)(m0 + row)     * DOUT + n0 + col) = r0;
            *(float2*)(out + (size_t)(m0 + row + 8) * DOUT + n0 + col) = r1;
        }
    }
}

// ---------------- launch ----------------
extern "C" void kernel_launch(void* const* d_in, const int* in_sizes, int n_in,
                              void* d_out, int out_size) {
    const float* x   = (const float*)d_in[0];
    const int*   qw  = (const int*)d_in[1];
    const int*   qb  = (const int*)d_in[2];
    const float* sc  = (const float*)d_in[3];
    const float* bsc = (const float*)d_in[4];
    float* out = (float*)d_out;

    cudaFuncSetAttribute(qlinear_gemm, cudaFuncAttributeMaxDynamicSharedMemorySize, SMEM_BYTES);

    convert_w_kernel<<<(DOUT * (size_t)DIN) / 4 / 256, 256>>>(qw);   // 65536 blocks
    convert_x_kernel<<<(TOKENS * (size_t)DIN) / 4 / 256, 256>>>(x);  // 32768 blocks
    // GEMM split into 4 M-chunks (2048 tokens each) so ncu (-s 5 -c 1) lands on it.
    for (int c = 0; c < 4; ++c)
        qlinear_gemm<<<8 * 128, 512, SMEM_BYTES>>>(qb, sc, bsc, out, c * 2048);
}